// round 1
// baseline (speedup 1.0000x reference)
#include <cuda_runtime.h>
#include <cuda_bf16.h>
#include <math.h>

// ---------------- dims ----------------
#define HID   2048
#define INTER 8192
#define QKV   8192
#define TV    4096
#define NVH   32
#define KD    128
#define VD    128
#define NKH   16
#define PROJ_ROWS (QKV + TV + 2*NVH)   // 12352
// proj layout offsets
#define OFF_Z   QKV            // 8192
#define OFF_A   (QKV + TV)     // 12288
#define OFF_B   (QKV + TV + NVH) // 12320

// d_out layout: x_out[2048] | new_conv_state[8192*4] | new_ssm_state[32*128*128]
#define OUT_CONV_OFF 2048
#define OUT_SSM_OFF  (2048 + QKV*4)    // 34816

// ---------------- scratch (no allocations allowed) ----------------
__device__ float g_h[HID];
__device__ float g_proj[PROJ_ROWS];
__device__ float g_conv_out[QKV];
__device__ float g_ygated[TV];
__device__ float g_x1[HID];
__device__ float g_hn[HID];
__device__ float g_t[INTER];

// ---------------- helpers ----------------
__device__ __forceinline__ float warp_sum(float v) {
#pragma unroll
    for (int o = 16; o > 0; o >>= 1) v += __shfl_down_sync(0xffffffffu, v, o);
    return v;
}

__device__ __forceinline__ float silu(float x) {
    return x / (1.0f + expf(-x));
}

// ---------------- 1: rmsnorm (2048 elems, 1 block of 256) ----------------
__global__ void k_rmsnorm(const float* __restrict__ x, const float* __restrict__ w,
                          float* __restrict__ out) {
    __shared__ float red[8];
    int t = threadIdx.x; // 256
    const float4* x4 = (const float4*)x;
    float s = 0.f;
    float4 v0 = x4[t];         // 0..255
    float4 v1 = x4[t + 256];   // 256..511
    s += v0.x*v0.x + v0.y*v0.y + v0.z*v0.z + v0.w*v0.w;
    s += v1.x*v1.x + v1.y*v1.y + v1.z*v1.z + v1.w*v1.w;
    s = warp_sum(s);
    if ((t & 31) == 0) red[t >> 5] = s;
    __syncthreads();
    float tot = 0.f;
#pragma unroll
    for (int i = 0; i < 8; i++) tot += red[i];
    float rstd = rsqrtf(tot / (float)HID + 1e-6f);
    const float4* w4 = (const float4*)w;
    float4* o4 = (float4*)out;
    float4 wa = w4[t], wb = w4[t + 256];
    float4 oa, ob;
    oa.x = v0.x * rstd * (1.f + wa.x); oa.y = v0.y * rstd * (1.f + wa.y);
    oa.z = v0.z * rstd * (1.f + wa.z); oa.w = v0.w * rstd * (1.f + wa.w);
    ob.x = v1.x * rstd * (1.f + wb.x); ob.y = v1.y * rstd * (1.f + wb.y);
    ob.z = v1.z * rstd * (1.f + wb.z); ob.w = v1.w * rstd * (1.f + wb.w);
    o4[t] = oa; o4[t + 256] = ob;
}

// ---------------- 2: in_proj GEMV 12352 x 2048, warp per row ----------------
__global__ void k_gemv_in(const float* __restrict__ W) {
    int row = blockIdx.x * 8 + (threadIdx.x >> 5);
    int lane = threadIdx.x & 31;
    const float4* w4 = (const float4*)(W + (size_t)row * HID);
    const float4* h4 = (const float4*)g_h;
    float acc = 0.f;
#pragma unroll
    for (int i = 0; i < 16; i++) {
        float4 a = w4[lane + i * 32];
        float4 b = h4[lane + i * 32];
        acc += a.x*b.x + a.y*b.y + a.z*b.z + a.w*b.w;
    }
    acc = warp_sum(acc);
    if (lane == 0) g_proj[row] = acc;
}

// ---------------- 3: conv state update + silu ----------------
__global__ void k_conv(const float* __restrict__ conv_state,
                       const float* __restrict__ conv_w,
                       float* __restrict__ out_conv_state) {
    int i = blockIdx.x * 256 + threadIdx.x; // 0..8191
    float4 cs = ((const float4*)conv_state)[i];
    float4 w  = ((const float4*)conv_w)[i];
    float mx = g_proj[i];
    float s = w.x * cs.y + w.y * cs.z + w.z * cs.w + w.w * mx;
    g_conv_out[i] = silu(s);
    float4 n; n.x = cs.y; n.y = cs.z; n.z = cs.w; n.w = mx;
    ((float4*)out_conv_state)[i] = n;
}

// ---------------- block reduce (128 threads) ----------------
__device__ __forceinline__ float block_sum128(float v, float* red) {
    v = warp_sum(v);
    int w = threadIdx.x >> 5, lane = threadIdx.x & 31;
    if (lane == 0) red[w] = v;
    __syncthreads();
    float s = red[0] + red[1] + red[2] + red[3];
    __syncthreads();
    return s;
}

// ---------------- 4: delta-rule update, 32 blocks x 128 threads ----------------
__global__ void k_delta(const float* __restrict__ ssm,
                        const float* __restrict__ A_log,
                        const float* __restrict__ dt_bias,
                        const float* __restrict__ norm_w,
                        float* __restrict__ out_ssm) {
    int h = blockIdx.x;   // head
    int v = threadIdx.x;  // value-dim column
    __shared__ float sk[KD], sq[KD], red[4];

    int kvh = h >> 1;
    float qraw = g_conv_out[kvh * KD + v];
    float kraw = g_conv_out[2048 + kvh * KD + v];
    float vval = g_conv_out[4096 + h * VD + v];

    float q2 = block_sum128(qraw * qraw, red);
    float k2 = block_sum128(kraw * kraw, red);
    float qn = qraw / fmaxf(sqrtf(q2), 1e-12f);
    float kn = kraw / fmaxf(sqrtf(k2), 1e-12f);
    sk[v] = kn;
    sq[v] = qn;
    __syncthreads();

    // per-head scalars (computed redundantly by each thread; cheap)
    float araw = g_proj[OFF_A + h] + dt_bias[h];
    float sp = (araw > 20.f) ? araw : log1pf(expf(araw));
    float decay = expf(-expf(A_log[h]) * sp);
    float beta = 1.f / (1.f + expf(-g_proj[OFF_B + h]));

    const float* S = ssm + (size_t)h * KD * VD + v;     // stride VD over k
    float Skv = 0.f;
#pragma unroll 8
    for (int k = 0; k < KD; k++) Skv += S[k * VD] * sk[k];
    float dl = vval - Skv;

    float* O = out_ssm + (size_t)h * KD * VD + v;
    float y = 0.f;
#pragma unroll 8
    for (int k = 0; k < KD; k++) {
        float ns = decay * S[k * VD] + beta * sk[k] * dl;
        O[k * VD] = ns;
        y += ns * sq[k];
    }

    float y2 = block_sum128(y * y, red);
    float rstd = rsqrtf(y2 / (float)VD + 1e-6f);
    float yn = y * rstd * norm_w[v];
    float z = g_proj[OFF_Z + h * VD + v];
    g_ygated[h * VD + v] = yn * silu(z);
}

// ---------------- 5: out_proj GEMV 2048 x 4096 + residual ----------------
__global__ void k_gemv_out(const float* __restrict__ W, const float* __restrict__ x) {
    int row = blockIdx.x * 8 + (threadIdx.x >> 5);
    int lane = threadIdx.x & 31;
    const float4* w4 = (const float4*)(W + (size_t)row * TV);
    const float4* y4 = (const float4*)g_ygated;
    float acc = 0.f;
#pragma unroll
    for (int i = 0; i < 32; i++) {
        float4 a = w4[lane + i * 32];
        float4 b = y4[lane + i * 32];
        acc += a.x*b.x + a.y*b.y + a.z*b.z + a.w*b.w;
    }
    acc = warp_sum(acc);
    if (lane == 0) g_x1[row] = x[row] + acc;
}

// ---------------- 7: fused gate/up GEMV 8192 x 2048 (x2) ----------------
__global__ void k_gateup(const float* __restrict__ Wg, const float* __restrict__ Wu) {
    int row = blockIdx.x * 8 + (threadIdx.x >> 5);
    int lane = threadIdx.x & 31;
    const float4* g4 = (const float4*)(Wg + (size_t)row * HID);
    const float4* u4 = (const float4*)(Wu + (size_t)row * HID);
    const float4* h4 = (const float4*)g_hn;
    float ag = 0.f, au = 0.f;
#pragma unroll
    for (int i = 0; i < 16; i++) {
        float4 b = h4[lane + i * 32];
        float4 a = g4[lane + i * 32];
        ag += a.x*b.x + a.y*b.y + a.z*b.z + a.w*b.w;
        float4 c = u4[lane + i * 32];
        au += c.x*b.x + c.y*b.y + c.z*b.z + c.w*b.w;
    }
    ag = warp_sum(ag);
    au = warp_sum(au);
    if (lane == 0) g_t[row] = silu(ag) * au;
}

// ---------------- 8: down GEMV 2048 x 8192 + residual ----------------
__global__ void k_down(const float* __restrict__ W, float* __restrict__ out) {
    int row = blockIdx.x * 8 + (threadIdx.x >> 5);
    int lane = threadIdx.x & 31;
    const float4* w4 = (const float4*)(W + (size_t)row * INTER);
    const float4* t4 = (const float4*)g_t;
    float acc = 0.f;
#pragma unroll 16
    for (int i = 0; i < 64; i++) {
        float4 a = w4[lane + i * 32];
        float4 b = t4[lane + i * 32];
        acc += a.x*b.x + a.y*b.y + a.z*b.z + a.w*b.w;
    }
    acc = warp_sum(acc);
    if (lane == 0) out[row] = g_x1[row] + acc;
}

// ---------------- launch ----------------
extern "C" void kernel_launch(void* const* d_in, const int* in_sizes, int n_in,
                              void* d_out, int out_size) {
    const float* x          = (const float*)d_in[0];
    const float* conv_state = (const float*)d_in[1];
    const float* ssm_state  = (const float*)d_in[2];
    const float* in_ln_w    = (const float*)d_in[3];
    const float* in_proj_w  = (const float*)d_in[4];
    const float* conv_w     = (const float*)d_in[5];
    const float* A_log      = (const float*)d_in[6];
    const float* dt_bias    = (const float*)d_in[7];
    const float* norm_w     = (const float*)d_in[8];
    const float* out_proj_w = (const float*)d_in[9];
    const float* post_ln_w  = (const float*)d_in[10];
    const float* gate_w     = (const float*)d_in[11];
    const float* up_w       = (const float*)d_in[12];
    const float* down_w     = (const float*)d_in[13];
    float* out = (float*)d_out;

    float* g_h_p;       cudaGetSymbolAddress((void**)&g_h_p, g_h);
    float* g_x1_p;      cudaGetSymbolAddress((void**)&g_x1_p, g_x1);
    float* g_hn_p;      cudaGetSymbolAddress((void**)&g_hn_p, g_hn);

    // 1. h = rmsnorm(x, in_ln_w)
    k_rmsnorm<<<1, 256>>>(x, in_ln_w, g_h_p);
    // 2. proj = in_proj_w @ h
    k_gemv_in<<<PROJ_ROWS / 8, 256>>>(in_proj_w);
    // 3. conv update (writes new_conv_state to d_out)
    k_conv<<<QKV / 256, 256>>>(conv_state, conv_w, out + OUT_CONV_OFF);
    // 4. delta rule (writes new_ssm_state to d_out)
    k_delta<<<NVH, 128>>>(ssm_state, A_log, dt_bias, norm_w, out + OUT_SSM_OFF);
    // 5. x1 = x + out_proj_w @ y_gated
    k_gemv_out<<<HID / 8, 256>>>(out_proj_w, x);
    // 6. hn = rmsnorm(x1, post_ln_w)
    k_rmsnorm<<<1, 256>>>(g_x1_p, post_ln_w, g_hn_p);
    // 7. t = silu(gate_w@hn) * (up_w@hn)
    k_gateup<<<INTER / 8, 256>>>(gate_w, up_w);
    // 8. x_out = x1 + down_w @ t
    k_down<<<HID / 8, 256>>>(down_w, out);
}

// round 2
// speedup vs baseline: 1.2229x; 1.2229x over previous
#include <cuda_runtime.h>
#include <cuda_bf16.h>
#include <math.h>

// ---------------- dims ----------------
#define HID   2048
#define INTER 8192
#define QKV   8192
#define TV    4096
#define NVH   32
#define KD    128
#define VD    128
#define NKH   16
#define PROJ_ROWS (QKV + TV + 2*NVH)   // 12352
#define OFF_Z   QKV              // 8192
#define OFF_A   (QKV + TV)       // 12288
#define OFF_B   (QKV + TV + NVH) // 12320

// d_out layout: x_out[2048] | new_conv_state[8192*4] | new_ssm_state[32*128*128]
#define OUT_CONV_OFF 2048
#define OUT_SSM_OFF  (2048 + QKV*4)    // 34816

// ---------------- scratch ----------------
__device__ float g_proj[PROJ_ROWS];
__device__ float g_conv_out[QKV];
__device__ float g_ygated[TV];
__device__ float g_x1[HID];
__device__ float g_t[INTER];

// ---------------- helpers ----------------
__device__ __forceinline__ float warp_sum(float v) {
#pragma unroll
    for (int o = 16; o > 0; o >>= 1) v += __shfl_down_sync(0xffffffffu, v, o);
    return v;
}
__device__ __forceinline__ float silu(float x) { return x / (1.0f + expf(-x)); }

__device__ __forceinline__ float block_sum256(float v, float* red) {
    v = warp_sum(v);
    int w = threadIdx.x >> 5, lane = threadIdx.x & 31;
    if (lane == 0) red[w] = v;
    __syncthreads();
    float s = 0.f;
#pragma unroll
    for (int i = 0; i < 8; i++) s += red[i];
    __syncthreads();
    return s;
}

__device__ __forceinline__ float block_sum512(float v, float* red) {
    v = warp_sum(v);
    int w = threadIdx.x >> 5, lane = threadIdx.x & 31;
    if (lane == 0) red[w] = v;
    __syncthreads();
    float s = 0.f;
#pragma unroll
    for (int i = 0; i < 16; i++) s += red[i];
    __syncthreads();
    return s;
}

// ---------------- fused rmsnorm into smem (256-thread blocks) ----------------
__device__ __forceinline__ void rmsnorm_to_smem(const float* __restrict__ x,
                                                const float* __restrict__ w,
                                                float* __restrict__ sh,  // [HID]
                                                float* __restrict__ red) // [8]
{
    int t = threadIdx.x; // 256
    const float4* x4 = (const float4*)x;
    float4 v0 = x4[t];
    float4 v1 = x4[t + 256];
    float s = v0.x*v0.x + v0.y*v0.y + v0.z*v0.z + v0.w*v0.w
            + v1.x*v1.x + v1.y*v1.y + v1.z*v1.z + v1.w*v1.w;
    s = block_sum256(s, red);
    float rstd = rsqrtf(s / (float)HID + 1e-6f);
    const float4* w4 = (const float4*)w;
    float4 wa = w4[t], wb = w4[t + 256];
    float4* sh4 = (float4*)sh;
    float4 oa, ob;
    oa.x = v0.x * rstd * (1.f + wa.x); oa.y = v0.y * rstd * (1.f + wa.y);
    oa.z = v0.z * rstd * (1.f + wa.z); oa.w = v0.w * rstd * (1.f + wa.w);
    ob.x = v1.x * rstd * (1.f + wb.x); ob.y = v1.y * rstd * (1.f + wb.y);
    ob.z = v1.z * rstd * (1.f + wb.z); ob.w = v1.w * rstd * (1.f + wb.w);
    sh4[t] = oa; sh4[t + 256] = ob;
    __syncthreads();
}

// ---------------- 1: in_proj GEMV 12352 x 2048 (fused in-rmsnorm) ----------------
__global__ void k_gemv_in(const float* __restrict__ W,
                          const float* __restrict__ x,
                          const float* __restrict__ ln_w) {
    __shared__ float sh[HID];
    __shared__ float red[8];
    rmsnorm_to_smem(x, ln_w, sh, red);

    int row = blockIdx.x * 8 + (threadIdx.x >> 5);
    int lane = threadIdx.x & 31;
    const float4* w4 = (const float4*)(W + (size_t)row * HID);
    const float4* h4 = (const float4*)sh;
    float acc = 0.f;
#pragma unroll
    for (int i = 0; i < 16; i++) {
        float4 a = w4[lane + i * 32];
        float4 b = h4[lane + i * 32];
        acc += a.x*b.x + a.y*b.y + a.z*b.z + a.w*b.w;
    }
    acc = warp_sum(acc);
    if (lane == 0) g_proj[row] = acc;
}

// ---------------- 2: conv state update + silu ----------------
__global__ void k_conv(const float* __restrict__ conv_state,
                       const float* __restrict__ conv_w,
                       float* __restrict__ out_conv_state) {
    int i = blockIdx.x * 256 + threadIdx.x; // 0..8191
    float4 cs = ((const float4*)conv_state)[i];
    float4 w  = ((const float4*)conv_w)[i];
    float mx = g_proj[i];
    float s = w.x * cs.y + w.y * cs.z + w.z * cs.w + w.w * mx;
    g_conv_out[i] = silu(s);
    float4 n; n.x = cs.y; n.y = cs.z; n.z = cs.w; n.w = mx;
    ((float4*)out_conv_state)[i] = n;
}

// ---------------- 3: delta-rule, 32 blocks x 512 threads (4-way k split) ----------------
__global__ void __launch_bounds__(512, 2)
k_delta(const float* __restrict__ ssm,
        const float* __restrict__ A_log,
        const float* __restrict__ dt_bias,
        const float* __restrict__ norm_w,
        float* __restrict__ out_ssm) {
    int h = blockIdx.x;          // head
    int tid = threadIdx.x;
    int kw = tid >> 7;           // 0..3 : k-chunk
    int v  = tid & 127;          // value column
    __shared__ float sk[KD], sq[KD], part[4][KD], red[16];

    int kvh = h >> 1;
    float qraw = g_conv_out[kvh * KD + v];
    float kraw = g_conv_out[2048 + kvh * KD + v];
    float vval = g_conv_out[4096 + h * VD + v];

    // l2-norm sums (each value counted 4x across kw groups)
    float q2 = block_sum512(qraw * qraw, red) * 0.25f;
    float k2 = block_sum512(kraw * kraw, red) * 0.25f;
    float qn = qraw / fmaxf(sqrtf(q2), 1e-12f);
    float kn = kraw / fmaxf(sqrtf(k2), 1e-12f);
    if (kw == 0) { sk[v] = kn; sq[v] = qn; }
    __syncthreads();

    // per-head scalars
    float araw = g_proj[OFF_A + h] + dt_bias[h];
    float sp = (araw > 20.f) ? araw : log1pf(expf(araw));
    float decay = expf(-expf(A_log[h]) * sp);
    float beta  = 1.f / (1.f + expf(-g_proj[OFF_B + h]));

    const float* S = ssm + (size_t)h * KD * VD + v;
    int k0 = kw * 32;

    // pass 1: partial Skv over this k-chunk
    float acc = 0.f;
#pragma unroll
    for (int i = 0; i < 32; i++) acc += S[(k0 + i) * VD] * sk[k0 + i];
    part[kw][v] = acc;
    __syncthreads();
    float Skv = part[0][v] + part[1][v] + part[2][v] + part[3][v];
    float dl = vval - Skv;
    __syncthreads();   // all reads of part done before pass-2 writes

    // pass 2: new state + partial y (S re-read from L2)
    float* O = out_ssm + (size_t)h * KD * VD + v;
    float yacc = 0.f;
#pragma unroll
    for (int i = 0; i < 32; i++) {
        int k = k0 + i;
        float ns = decay * S[k * VD] + beta * sk[k] * dl;
        O[k * VD] = ns;
        yacc += ns * sq[k];
    }
    part[kw][v] = yacc;
    __syncthreads();
    float y = part[0][v] + part[1][v] + part[2][v] + part[3][v];

    // y rmsnorm + gate (each y counted 4x)
    float y2 = block_sum512(y * y, red) * 0.25f;
    float rstd = rsqrtf(y2 / (float)VD + 1e-6f);
    if (kw == 0) {
        float yn = y * rstd * norm_w[v];
        float z = g_proj[OFF_Z + h * VD + v];
        g_ygated[h * VD + v] = yn * silu(z);
    }
}

// ---------------- 4: out_proj GEMV 2048 x 4096 + residual ----------------
__global__ void k_gemv_out(const float* __restrict__ W, const float* __restrict__ x) {
    int row = blockIdx.x * 8 + (threadIdx.x >> 5);
    int lane = threadIdx.x & 31;
    const float4* w4 = (const float4*)(W + (size_t)row * TV);
    const float4* y4 = (const float4*)g_ygated;
    float acc = 0.f;
#pragma unroll
    for (int i = 0; i < 32; i++) {
        float4 a = w4[lane + i * 32];
        float4 b = y4[lane + i * 32];
        acc += a.x*b.x + a.y*b.y + a.z*b.z + a.w*b.w;
    }
    acc = warp_sum(acc);
    if (lane == 0) g_x1[row] = x[row] + acc;
}

// ---------------- 5: fused gate/up GEMV 8192 x 2048 x2 (fused post-rmsnorm) ----------------
__global__ void k_gateup(const float* __restrict__ Wg, const float* __restrict__ Wu,
                         const float* __restrict__ post_ln_w) {
    __shared__ float sh[HID];
    __shared__ float red[8];
    rmsnorm_to_smem(g_x1, post_ln_w, sh, red);

    int row = blockIdx.x * 8 + (threadIdx.x >> 5);
    int lane = threadIdx.x & 31;
    const float4* g4 = (const float4*)(Wg + (size_t)row * HID);
    const float4* u4 = (const float4*)(Wu + (size_t)row * HID);
    const float4* h4 = (const float4*)sh;
    float ag = 0.f, au = 0.f;
#pragma unroll
    for (int i = 0; i < 16; i++) {
        float4 b = h4[lane + i * 32];
        float4 a = g4[lane + i * 32];
        ag += a.x*b.x + a.y*b.y + a.z*b.z + a.w*b.w;
        float4 c = u4[lane + i * 32];
        au += c.x*b.x + c.y*b.y + c.z*b.z + c.w*b.w;
    }
    ag = warp_sum(ag);
    au = warp_sum(au);
    if (lane == 0) g_t[row] = silu(ag) * au;
}

// ---------------- 6: down GEMV 2048 x 8192 + residual ----------------
__global__ void k_down(const float* __restrict__ W, float* __restrict__ out) {
    int row = blockIdx.x * 8 + (threadIdx.x >> 5);
    int lane = threadIdx.x & 31;
    const float4* w4 = (const float4*)(W + (size_t)row * INTER);
    const float4* t4 = (const float4*)g_t;
    float acc = 0.f;
#pragma unroll 16
    for (int i = 0; i < 64; i++) {
        float4 a = w4[lane + i * 32];
        float4 b = t4[lane + i * 32];
        acc += a.x*b.x + a.y*b.y + a.z*b.z + a.w*b.w;
    }
    acc = warp_sum(acc);
    if (lane == 0) out[row] = g_x1[row] + acc;
}

// ---------------- launch ----------------
extern "C" void kernel_launch(void* const* d_in, const int* in_sizes, int n_in,
                              void* d_out, int out_size) {
    const float* x          = (const float*)d_in[0];
    const float* conv_state = (const float*)d_in[1];
    const float* ssm_state  = (const float*)d_in[2];
    const float* in_ln_w    = (const float*)d_in[3];
    const float* in_proj_w  = (const float*)d_in[4];
    const float* conv_w     = (const float*)d_in[5];
    const float* A_log      = (const float*)d_in[6];
    const float* dt_bias    = (const float*)d_in[7];
    const float* norm_w     = (const float*)d_in[8];
    const float* out_proj_w = (const float*)d_in[9];
    const float* post_ln_w  = (const float*)d_in[10];
    const float* gate_w     = (const float*)d_in[11];
    const float* up_w       = (const float*)d_in[12];
    const float* down_w     = (const float*)d_in[13];
    float* out = (float*)d_out;

    // 1. proj = in_proj_w @ rmsnorm(x)
    k_gemv_in<<<PROJ_ROWS / 8, 256>>>(in_proj_w, x, in_ln_w);
    // 2. conv update (writes new_conv_state to d_out)
    k_conv<<<QKV / 256, 256>>>(conv_state, conv_w, out + OUT_CONV_OFF);
    // 3. delta rule (writes new_ssm_state to d_out)
    k_delta<<<NVH, 512>>>(ssm_state, A_log, dt_bias, norm_w, out + OUT_SSM_OFF);
    // 4. x1 = x + out_proj_w @ y_gated
    k_gemv_out<<<HID / 8, 256>>>(out_proj_w, x);
    // 5. t = silu(gate_w@hn) * (up_w@hn), hn = rmsnorm(x1)
    k_gateup<<<INTER / 8, 256>>>(gate_w, up_w, post_ln_w);
    // 6. x_out = x1 + down_w @ t
    k_down<<<HID / 8, 256>>>(down_w, out);
}

// round 3
// speedup vs baseline: 1.3964x; 1.1418x over previous
#include <cuda_runtime.h>
#include <cuda_bf16.h>
#include <math.h>

// ---------------- dims ----------------
#define HID   2048
#define INTER 8192
#define QKV   8192
#define TV    4096
#define NVH   32
#define KD    128
#define VD    128
#define NKH   16
#define PROJ_ROWS (QKV + TV + 2*NVH)   // 12352
#define OFF_Z   QKV              // 8192
#define OFF_A   (QKV + TV)       // 12288
#define OFF_B   (QKV + TV + NVH) // 12320

// d_out layout: x_out[2048] | new_conv_state[8192*4] | new_ssm_state[32*128*128]
#define OUT_CONV_OFF 2048
#define OUT_SSM_OFF  (2048 + QKV*4)    // 34816

// ---------------- scratch ----------------
__device__ float g_proj[PROJ_ROWS];
__device__ float g_conv_out[QKV];
__device__ float g_ygated[TV];
__device__ float g_x1[HID];
__device__ float g_t[INTER];

// ---------------- helpers ----------------
__device__ __forceinline__ float warp_sum(float v) {
#pragma unroll
    for (int o = 16; o > 0; o >>= 1) v += __shfl_down_sync(0xffffffffu, v, o);
    return v;
}
__device__ __forceinline__ float silu(float x) { return x / (1.0f + expf(-x)); }

__device__ __forceinline__ float4 ldcs4(const float4* p) { return __ldcs(p); }

__device__ __forceinline__ float block_sum256(float v, float* red) {
    v = warp_sum(v);
    int w = threadIdx.x >> 5, lane = threadIdx.x & 31;
    if (lane == 0) red[w] = v;
    __syncthreads();
    float s = 0.f;
#pragma unroll
    for (int i = 0; i < 8; i++) s += red[i];
    __syncthreads();
    return s;
}

__device__ __forceinline__ float block_sum512(float v, float* red) {
    v = warp_sum(v);
    int w = threadIdx.x >> 5, lane = threadIdx.x & 31;
    if (lane == 0) red[w] = v;
    __syncthreads();
    float s = 0.f;
#pragma unroll
    for (int i = 0; i < 16; i++) s += red[i];
    __syncthreads();
    return s;
}

// ---------------- fused rmsnorm into smem (256-thread blocks) ----------------
__device__ __forceinline__ void rmsnorm_to_smem(const float* __restrict__ x,
                                                const float* __restrict__ w,
                                                float* __restrict__ sh,  // [HID]
                                                float* __restrict__ red) // [8]
{
    int t = threadIdx.x; // 256
    const float4* x4 = (const float4*)x;
    float4 v0 = x4[t];
    float4 v1 = x4[t + 256];
    float s = v0.x*v0.x + v0.y*v0.y + v0.z*v0.z + v0.w*v0.w
            + v1.x*v1.x + v1.y*v1.y + v1.z*v1.z + v1.w*v1.w;
    s = block_sum256(s, red);
    float rstd = rsqrtf(s / (float)HID + 1e-6f);
    const float4* w4 = (const float4*)w;
    float4 wa = w4[t], wb = w4[t + 256];
    float4* sh4 = (float4*)sh;
    float4 oa, ob;
    oa.x = v0.x * rstd * (1.f + wa.x); oa.y = v0.y * rstd * (1.f + wa.y);
    oa.z = v0.z * rstd * (1.f + wa.z); oa.w = v0.w * rstd * (1.f + wa.w);
    ob.x = v1.x * rstd * (1.f + wb.x); ob.y = v1.y * rstd * (1.f + wb.y);
    ob.z = v1.z * rstd * (1.f + wb.z); ob.w = v1.w * rstd * (1.f + wb.w);
    sh4[t] = oa; sh4[t + 256] = ob;
    __syncthreads();
}

// ---------------- 1: in_proj GEMV 12352 x 2048 (fused in-rmsnorm) ----------------
__global__ void k_gemv_in(const float* __restrict__ W,
                          const float* __restrict__ x,
                          const float* __restrict__ ln_w) {
    __shared__ float sh[HID];
    __shared__ float red[8];
    rmsnorm_to_smem(x, ln_w, sh, red);

    int row = blockIdx.x * 8 + (threadIdx.x >> 5);
    int lane = threadIdx.x & 31;
    const float4* w4 = (const float4*)(W + (size_t)row * HID);
    const float4* h4 = (const float4*)sh;
    float acc = 0.f;
#pragma unroll
    for (int i = 0; i < 16; i++) {
        float4 a = ldcs4(w4 + lane + i * 32);
        float4 b = h4[lane + i * 32];
        acc += a.x*b.x + a.y*b.y + a.z*b.z + a.w*b.w;
    }
    acc = warp_sum(acc);
    if (lane == 0) g_proj[row] = acc;
}

// ---------------- 2: conv state update + silu ----------------
__global__ void k_conv(const float* __restrict__ conv_state,
                       const float* __restrict__ conv_w,
                       float* __restrict__ out_conv_state) {
    int i = blockIdx.x * 256 + threadIdx.x; // 0..8191
    float4 cs = ((const float4*)conv_state)[i];
    float4 w  = ((const float4*)conv_w)[i];
    float mx = g_proj[i];
    float s = w.x * cs.y + w.y * cs.z + w.z * cs.w + w.w * mx;
    g_conv_out[i] = silu(s);
    float4 n; n.x = cs.y; n.y = cs.z; n.z = cs.w; n.w = mx;
    ((float4*)out_conv_state)[i] = n;
}

// ---------------- 3: delta-rule, 32 blocks x 512 threads (4-way k split) ----------------
__global__ void __launch_bounds__(512, 2)
k_delta(const float* __restrict__ ssm,
        const float* __restrict__ A_log,
        const float* __restrict__ dt_bias,
        const float* __restrict__ norm_w,
        float* __restrict__ out_ssm) {
    int h = blockIdx.x;          // head
    int tid = threadIdx.x;
    int kw = tid >> 7;           // 0..3 : k-chunk
    int v  = tid & 127;          // value column
    __shared__ float sk[KD], sq[KD], part[4][KD], red[16];

    int kvh = h >> 1;
    float qraw = g_conv_out[kvh * KD + v];
    float kraw = g_conv_out[2048 + kvh * KD + v];
    float vval = g_conv_out[4096 + h * VD + v];

    // l2-norm sums (each value counted 4x across kw groups)
    float q2 = block_sum512(qraw * qraw, red) * 0.25f;
    float k2 = block_sum512(kraw * kraw, red) * 0.25f;
    float qn = qraw / fmaxf(sqrtf(q2), 1e-12f);
    float kn = kraw / fmaxf(sqrtf(k2), 1e-12f);
    if (kw == 0) { sk[v] = kn; sq[v] = qn; }
    __syncthreads();

    // per-head scalars
    float araw = g_proj[OFF_A + h] + dt_bias[h];
    float sp = (araw > 20.f) ? araw : log1pf(expf(araw));
    float decay = expf(-expf(A_log[h]) * sp);
    float beta  = 1.f / (1.f + expf(-g_proj[OFF_B + h]));

    const float* S = ssm + (size_t)h * KD * VD + v;
    int k0 = kw * 32;

    // pass 1: partial Skv over this k-chunk
    float acc = 0.f;
#pragma unroll
    for (int i = 0; i < 32; i++) acc += S[(k0 + i) * VD] * sk[k0 + i];
    part[kw][v] = acc;
    __syncthreads();
    float Skv = part[0][v] + part[1][v] + part[2][v] + part[3][v];
    float dl = vval - Skv;
    __syncthreads();   // all reads of part done before pass-2 writes

    // pass 2: new state + partial y (S re-read from L2)
    float* O = out_ssm + (size_t)h * KD * VD + v;
    float yacc = 0.f;
#pragma unroll
    for (int i = 0; i < 32; i++) {
        int k = k0 + i;
        float ns = decay * S[k * VD] + beta * sk[k] * dl;
        O[k * VD] = ns;
        yacc += ns * sq[k];
    }
    part[kw][v] = yacc;
    __syncthreads();
    float y = part[0][v] + part[1][v] + part[2][v] + part[3][v];

    // y rmsnorm + gate (each y counted 4x)
    float y2 = block_sum512(y * y, red) * 0.25f;
    float rstd = rsqrtf(y2 / (float)VD + 1e-6f);
    if (kw == 0) {
        float yn = y * rstd * norm_w[v];
        float z = g_proj[OFF_Z + h * VD + v];
        g_ygated[h * VD + v] = yn * silu(z);
    }
}

// ---------------- 4: out_proj GEMV, block-per-row, 128 thr (split-K) ----------------
__global__ void __launch_bounds__(128)
k_gemv_out(const float* __restrict__ W, const float* __restrict__ x) {
    __shared__ float red[4];
    int row = blockIdx.x;
    int t = threadIdx.x; // 128
    const float4* w4 = (const float4*)(W + (size_t)row * TV);
    const float4* y4 = (const float4*)g_ygated;
    float acc = 0.f;
#pragma unroll
    for (int i = 0; i < 8; i++) {
        float4 a = ldcs4(w4 + t + i * 128);
        float4 b = y4[t + i * 128];
        acc += a.x*b.x + a.y*b.y + a.z*b.z + a.w*b.w;
    }
    acc = warp_sum(acc);
    int w = t >> 5, lane = t & 31;
    if (lane == 0) red[w] = acc;
    __syncthreads();
    if (t == 0) g_x1[row] = x[row] + red[0] + red[1] + red[2] + red[3];
}

// ---------------- 5: fused gate/up GEMV 8192 x 2048 x2 (fused post-rmsnorm) ----------------
__global__ void k_gateup(const float* __restrict__ Wg, const float* __restrict__ Wu,
                         const float* __restrict__ post_ln_w) {
    __shared__ float sh[HID];
    __shared__ float red[8];
    rmsnorm_to_smem(g_x1, post_ln_w, sh, red);

    int row = blockIdx.x * 8 + (threadIdx.x >> 5);
    int lane = threadIdx.x & 31;
    const float4* g4 = (const float4*)(Wg + (size_t)row * HID);
    const float4* u4 = (const float4*)(Wu + (size_t)row * HID);
    const float4* h4 = (const float4*)sh;
    float ag = 0.f, au = 0.f;
#pragma unroll
    for (int i = 0; i < 16; i++) {
        float4 b = h4[lane + i * 32];
        float4 a = ldcs4(g4 + lane + i * 32);
        ag += a.x*b.x + a.y*b.y + a.z*b.z + a.w*b.w;
        float4 c = ldcs4(u4 + lane + i * 32);
        au += c.x*b.x + c.y*b.y + c.z*b.z + c.w*b.w;
    }
    ag = warp_sum(ag);
    au = warp_sum(au);
    if (lane == 0) g_t[row] = silu(ag) * au;
}

// ---------------- 6: down GEMV, block-per-row, 256 thr (split-K) + residual ----------------
__global__ void __launch_bounds__(256)
k_down(const float* __restrict__ W, float* __restrict__ out) {
    __shared__ float red[8];
    int row = blockIdx.x;
    int t = threadIdx.x; // 256
    const float4* w4 = (const float4*)(W + (size_t)row * INTER);
    const float4* t4 = (const float4*)g_t;
    float acc = 0.f;
#pragma unroll
    for (int i = 0; i < 8; i++) {
        float4 a = ldcs4(w4 + t + i * 256);
        float4 b = t4[t + i * 256];
        acc += a.x*b.x + a.y*b.y + a.z*b.z + a.w*b.w;
    }
    acc = block_sum256(acc, red);
    if (t == 0) out[row] = g_x1[row] + acc;
}

// ---------------- launch ----------------
extern "C" void kernel_launch(void* const* d_in, const int* in_sizes, int n_in,
                              void* d_out, int out_size) {
    const float* x          = (const float*)d_in[0];
    const float* conv_state = (const float*)d_in[1];
    const float* ssm_state  = (const float*)d_in[2];
    const float* in_ln_w    = (const float*)d_in[3];
    const float* in_proj_w  = (const float*)d_in[4];
    const float* conv_w     = (const float*)d_in[5];
    const float* A_log      = (const float*)d_in[6];
    const float* dt_bias    = (const float*)d_in[7];
    const float* norm_w     = (const float*)d_in[8];
    const float* out_proj_w = (const float*)d_in[9];
    const float* post_ln_w  = (const float*)d_in[10];
    const float* gate_w     = (const float*)d_in[11];
    const float* up_w       = (const float*)d_in[12];
    const float* down_w     = (const float*)d_in[13];
    float* out = (float*)d_out;

    // 1. proj = in_proj_w @ rmsnorm(x)
    k_gemv_in<<<PROJ_ROWS / 8, 256>>>(in_proj_w, x, in_ln_w);
    // 2. conv update (writes new_conv_state to d_out)
    k_conv<<<QKV / 256, 256>>>(conv_state, conv_w, out + OUT_CONV_OFF);
    // 3. delta rule (writes new_ssm_state to d_out)
    k_delta<<<NVH, 512>>>(ssm_state, A_log, dt_bias, norm_w, out + OUT_SSM_OFF);
    // 4. x1 = x + out_proj_w @ y_gated   (block-per-row split-K)
    k_gemv_out<<<HID, 128>>>(out_proj_w, x);
    // 5. t = silu(gate_w@hn) * (up_w@hn), hn = rmsnorm(x1)
    k_gateup<<<INTER / 8, 256>>>(gate_w, up_w, post_ln_w);
    // 6. x_out = x1 + down_w @ t          (block-per-row split-K)
    k_down<<<HID, 256>>>(down_w, out);
}